// round 16
// baseline (speedup 1.0000x reference)
#include <cuda_runtime.h>
#include <cuda_fp16.h>
#include <cstdint>

#define DEVINL __device__ __forceinline__

constexpr int kB = 4, kS = 2048, kD = 1024, kH = 16, kHD = 64;
constexpr int kM = kB * kS;  // 8192 rows for QKV GEMM
constexpr float kLog2e = 1.44269504088896f;

// All fp16 (same 10-bit mantissa as tf32):
// g_q, g_k : [B,H][S][64]   g_v : [B,H][64][S] (V^T, rows pre-scaled by
// e^mask -> mask folded into numerator)   g_x : rounded X
// g_wt : rounded W^T ([n][k]) per z.  Q pre-scaled by hd^-0.5 * log2(e).
// g_wexp[b][k] = fp16(e^mask) -> row-sum weights (denominator fold).
__device__ __half g_q[(long long)kB * kH * kS * kHD];
__device__ __half g_k[(long long)kB * kH * kS * kHD];
__device__ __half g_v[(long long)kB * kH * kS * kHD];
__device__ __half g_x[(long long)kM * kD];
__device__ __half g_wt[3ll * kD * kD];
__device__ __half g_wexp[kB * kS];

DEVINL uint32_t smem_u32(const void* p) {
    return (uint32_t)__cvta_generic_to_shared(p);
}
DEVINL void cp_async16(uint32_t dst, const void* src) {
    asm volatile("cp.async.cg.shared.global [%0], [%1], 16;\n" ::"r"(dst), "l"(src));
}
DEVINL void cp_commit() { asm volatile("cp.async.commit_group;\n" ::: "memory"); }
template <int N> DEVINL void cp_wait() {
    asm volatile("cp.async.wait_group %0;\n" ::"n"(N) : "memory");
}

DEVINL uint32_t packh2(float lo, float hi) {
    __half2 h = __floats2half2_rn(lo, hi);
    return *reinterpret_cast<uint32_t*>(&h);
}
// Packed fp16x2 exponential (base 2): one MUFU op for two values.
DEVINL uint32_t ex2h2(uint32_t x) {
    uint32_t r;
    asm("ex2.approx.f16x2 %0, %1;" : "=r"(r) : "r"(x));
    return r;
}

DEVINL void mma_f16(float* c, const uint32_t* a, uint32_t b0, uint32_t b1) {
    asm volatile(
        "mma.sync.aligned.m16n8k16.row.col.f32.f16.f16.f32 "
        "{%0,%1,%2,%3}, {%4,%5,%6,%7}, {%8,%9}, {%0,%1,%2,%3};\n"
        : "+f"(c[0]), "+f"(c[1]), "+f"(c[2]), "+f"(c[3])
        : "r"(a[0]), "r"(a[1]), "r"(a[2]), "r"(a[3]), "r"(b0), "r"(b1));
}

DEVINL void ldsm4(uint32_t* r, uint32_t addr) {
    asm volatile(
        "ldmatrix.sync.aligned.m8n8.x4.shared.b16 {%0,%1,%2,%3}, [%4];\n"
        : "=r"(r[0]), "=r"(r[1]), "=r"(r[2]), "=r"(r[3]) : "r"(addr));
}

// ======================= Stage 0: prep =======================
__global__ __launch_bounds__(256) void prep_wt_kernel(
    const float* __restrict__ Wq, const float* __restrict__ Wk,
    const float* __restrict__ Wv)
{
    __shared__ float t[32][33];
    const int z = blockIdx.z;
    const float* W = (z == 0) ? Wq : (z == 1) ? Wk : Wv;
    __half* outp = g_wt + (long long)z * kD * kD;
    const int n0 = blockIdx.x * 32, k0 = blockIdx.y * 32;
    const int tx = threadIdx.x & 31, ty = threadIdx.x >> 5;  // 32 x 8
    #pragma unroll
    for (int r = ty; r < 32; r += 8)
        t[r][tx] = W[(long long)(k0 + r) * kD + n0 + tx];
    __syncthreads();
    #pragma unroll
    for (int r = ty; r < 32; r += 8)
        outp[(long long)(n0 + r) * kD + k0 + tx] = __float2half_rn(t[tx][r]);
}

__global__ __launch_bounds__(256) void prep_x_kernel(const float* __restrict__ X,
                                                     const float* __restrict__ mask)
{
    const long long n4 = (long long)kM * kD / 4;
    const float4* src = (const float4*)X;
    uint2* dst = (uint2*)g_x;
    for (long long i = blockIdx.x * 256 + threadIdx.x; i < n4;
         i += (long long)gridDim.x * 256) {
        float4 v = src[i];
        uint2 o;
        o.x = packh2(v.x, v.y);
        o.y = packh2(v.z, v.w);
        dst[i] = o;
    }
    // w = e^mask (row-sum weights), 8192 elements
    for (int i = blockIdx.x * 256 + threadIdx.x; i < kB * kS;
         i += gridDim.x * 256)
        g_wexp[i] = __float2half_rn(__expf(mask[i]));
}

// ======================= Stage 1: QKV projections (fp16 mma) ============
// 128x128 CTA tile, k-step 64, 2-stage ring, one barrier/iter, 2 CTAs/SM.
constexpr int STRH = 72;  // fp16 stride: 144B rows -> conflict-free ldmatrix
constexpr int GEMM_SMEM_BYTES = 2 * 2 * 128 * STRH * 2;  // 73728

__global__ __launch_bounds__(256) void qkv_kernel(
    const float* __restrict__ bq, const float* __restrict__ bk,
    const float* __restrict__ bv, const float* __restrict__ mask)
{
    extern __shared__ __align__(16) char smraw[];
    __half* As = (__half*)smraw;                 // 2 x 128 x STRH
    __half* Bs = As + 2 * 128 * STRH;            // 2 x 128 x STRH

    const int z = blockIdx.z;
    const float* bia = (z == 0) ? bq : (z == 1) ? bk : bv;
    __half* outp     = (z == 0) ? g_q : (z == 1) ? g_k : g_v;
    // Q pre-scaled by hd^-0.5 * log2e -> scores land in log2 domain.
    const float scl  = (z == 0) ? 0.125f * kLog2e : 1.0f;
    const __half* wt = g_wt + (long long)z * kD * kD;

    const int bm = blockIdx.y * 128;
    const int bn = blockIdx.x * 128;
    const int tid = threadIdx.x;
    const int wid = tid >> 5, lane = tid & 31;
    const int wm = (wid >> 2) * 64, wn = (wid & 3) * 32;
    const int g = lane >> 2, t = lane & 3;
    const int lrow = lane & 7;
    const int lt8 = (lane >> 3) & 1, lt16 = (lane >> 4) & 1;

    float acc[4][4][4];
    #pragma unroll
    for (int mt = 0; mt < 4; ++mt)
        #pragma unroll
        for (int nt = 0; nt < 4; ++nt)
            #pragma unroll
            for (int i = 0; i < 4; ++i) acc[mt][nt][i] = 0.0f;

    auto load_stage = [&](int st, int k0) {
        __half* A  = As + st * 128 * STRH;
        __half* Bm = Bs + st * 128 * STRH;
        #pragma unroll
        for (int c = 0; c < 4; ++c) {
            const int ch = tid + c * 256;
            const int r = ch >> 3, cc = (ch & 7) * 8;
            cp_async16(smem_u32(A + r * STRH + cc),
                       g_x + (long long)(bm + r) * kD + k0 + cc);
            cp_async16(smem_u32(Bm + r * STRH + cc),
                       wt + (long long)(bn + r) * kD + k0 + cc);
        }
        cp_commit();
    };

    load_stage(0, 0);
    #pragma unroll 1
    for (int i = 0; i < 16; ++i) {
        const int st = i & 1;
        cp_wait<0>();      // own chunks of stage i landed
        __syncthreads();   // stage i visible; all reads of stage i^1 done
        if (i + 1 < 16)
            load_stage(st ^ 1, (i + 1) * 64);  // overlaps compute below

        const uint32_t a_base = smem_u32(As) + st * 128 * STRH * 2 +
            ((wm + lrow + lt8 * 8) * STRH + lt16 * 8) * 2;
        const uint32_t b_base = smem_u32(Bs) + st * 128 * STRH * 2 +
            ((wn + lrow + lt8 * 8) * STRH + lt16 * 8) * 2;

        #pragma unroll
        for (int kc = 0; kc < 4; ++kc) {
            uint32_t af[4][4], bf[2][4];
            #pragma unroll
            for (int mt = 0; mt < 4; ++mt)
                ldsm4(af[mt], a_base + (mt * 16 * STRH + kc * 16) * 2);
            #pragma unroll
            for (int ntp = 0; ntp < 2; ++ntp)
                ldsm4(bf[ntp], b_base + (ntp * 16 * STRH + kc * 16) * 2);
            #pragma unroll
            for (int mt = 0; mt < 4; ++mt)
                #pragma unroll
                for (int ntp = 0; ntp < 2; ++ntp) {
                    mma_f16(acc[mt][ntp * 2 + 0], af[mt], bf[ntp][0], bf[ntp][2]);
                    mma_f16(acc[mt][ntp * 2 + 1], af[mt], bf[ntp][1], bf[ntp][3]);
                }
        }
    }

    // Epilogue: + bias, * scale (Q) or * e^mask (V), fp16-round, scatter.
    #pragma unroll
    for (int mt = 0; mt < 4; ++mt) {
        // per (mt, rr) the m-row (and thus key index ss) is fixed
        float wv[2] = {1.0f, 1.0f};
        int bbr[2], ssr[2];
        #pragma unroll
        for (int rr = 0; rr < 2; ++rr) {
            const int m = bm + wm + mt * 16 + g + rr * 8;
            bbr[rr] = m >> 11;
            ssr[rr] = m & 2047;
            if (z == 2) wv[rr] = __expf(mask[bbr[rr] * kS + ssr[rr]]);
        }
        #pragma unroll
        for (int nt = 0; nt < 4; ++nt) {
            const int col = bn + wn + nt * 8 + 2 * t;  // even
            const int hh = col >> 6, d0 = col & 63;
            const float b0 = bia[col], b1 = bia[col + 1];
            #pragma unroll
            for (int rr = 0; rr < 2; ++rr) {
                const int bb = bbr[rr], ss = ssr[rr];
                if (z < 2) {
                    __half2 v;
                    v.x = __float2half_rn((acc[mt][nt][rr * 2 + 0] + b0) * scl);
                    v.y = __float2half_rn((acc[mt][nt][rr * 2 + 1] + b1) * scl);
                    *(__half2*)&outp[((long long)(bb * kH + hh) * kS + ss) * kHD + d0] = v;
                } else {  // V^T: [b,h][d][s], rows scaled by e^mask
                    const long long base = ((long long)(bb * kH + hh) * kHD + d0) * kS + ss;
                    outp[base]      = __float2half_rn((acc[mt][nt][rr * 2 + 0] + b0) * wv[rr]);
                    outp[base + kS] = __float2half_rn((acc[mt][nt][rr * 2 + 1] + b1) * wv[rr]);
                }
            }
        }
    }
}

// ======================= Stage 2: flash attention (fp16 mma) ============
// CTA = (b,h, 128 q-rows), 4 warps x 32 rows (2 m-tiles). Fixed-max softmax
// P = 2^S with PACKED fp16x2 exponentials (pack S first, one ex2.f16x2 per
// pair: halves MUFU occupancy and drops 32 instr/thread-iter). Mask folded
// into V rows + row-sum weights w. Row sums = P @ w on the tensor pipe.
// 3-stage ring, one barrier/iter, K/V b-frags shared across both m-tiles.
constexpr int ATTN_SMEM_BYTES =
    128 * STRH * 2 + 3 * (2 * 64 * STRH * 2) + 3 * 64 * 2;  // 74112

__global__ __launch_bounds__(128, 2) void attn_kernel(float* __restrict__ out)
{
    extern __shared__ __align__(16) char smraw[];
    __half* Qs = (__half*)smraw;          // 128 x STRH
    __half* Kb = Qs + 128 * STRH;         // 3 x 64 x STRH (rows s, cols d)
    __half* Vb = Kb + 3 * 64 * STRH;      // 3 x 64 x STRH (rows d, cols s)
    __half* Wb = Vb + 3 * 64 * STRH;      // 3 x 64 (w = e^mask per key)

    const int bh = blockIdx.y;
    const int b = bh >> 4, h = bh & 15;
    const int q0 = blockIdx.x * 128;
    const int tid = threadIdx.x, wid = tid >> 5, lane = tid & 31;
    const int g = lane >> 2, t = lane & 3;
    const int lrow = lane & 7;
    const int lt8 = (lane >> 3) & 1, lt16 = (lane >> 4) & 1;

    const __half* qptr = g_q + ((long long)bh * kS + q0) * kHD;
    const __half* kptr = g_k + (long long)bh * kS * kHD;
    const __half* vptr = g_v + (long long)bh * kHD * kS;  // [d][s]
    const __half* wptr = g_wexp + b * kS;

    // ---- stage Q (128 x 64 fp16) into Qs (stays for whole kernel) ----
    #pragma unroll
    for (int i = 0; i < 8; ++i) {
        const int ch = tid + i * 128;
        const int r = ch >> 3, c = (ch & 7) * 8;
        *(uint4*)&Qs[r * STRH + c] = *(const uint4*)&qptr[(long long)r * kHD + c];
    }

    auto prefetch = [&](int st, int k0) {
        __half* Kd = Kb + st * 64 * STRH;
        __half* Vd = Vb + st * 64 * STRH;
        #pragma unroll
        for (int i = 0; i < 4; ++i) {
            const int ch = tid + i * 128;
            const int r = ch >> 3, c = (ch & 7) * 8;
            cp_async16(smem_u32(Kd + r * STRH + c),
                       kptr + (long long)(k0 + r) * kHD + c);
            cp_async16(smem_u32(Vd + r * STRH + c),
                       vptr + (long long)r * kS + k0 + c);
        }
        if (tid < 8)
            cp_async16(smem_u32(Wb + st * 64 + tid * 8), wptr + k0 + tid * 8);
        cp_commit();
    };

    float o[2][8][4];
    #pragma unroll
    for (int mt = 0; mt < 2; ++mt)
        #pragma unroll
        for (int nv = 0; nv < 8; ++nv)
            #pragma unroll
            for (int i = 0; i < 4; ++i) o[mt][nv][i] = 0.0f;
    float lacc[2][4];  // row-sum c-frags (P @ w)
    #pragma unroll
    for (int mt = 0; mt < 2; ++mt)
        #pragma unroll
        for (int i = 0; i < 4; ++i) lacc[mt][i] = 0.0f;

    prefetch(0, 0);
    prefetch(1, 64);
    __syncthreads();  // Q staged + visible before first LDSM

    const uint32_t qsbase = smem_u32(Qs) +
        ((wid * 32 + lrow + lt8 * 8) * STRH + lt16 * 8) * 2;

    constexpr int NIT = kS / 64;  // 32
    #pragma unroll 1
    for (int it = 0; it < NIT; ++it) {
        const int st = it - (it / 3) * 3;  // it % 3
        if (it + 2 < NIT) {
            cp_wait<1>();       // stage it's data landed (it+1 still pending)
            __syncthreads();    // publish stage it; fences reads of stage (it+2)%3
            const int st2 = (it + 2) - ((it + 2) / 3) * 3;
            prefetch(st2, (it + 2) * 64);
        } else {
            cp_wait<0>();
            __syncthreads();
        }

        const uint32_t kbase = smem_u32(Kb) + st * 64 * STRH * 2 +
            ((lrow + lt8 * 8) * STRH + lt16 * 8) * 2;
        const uint32_t vbase = smem_u32(Vb) + st * 64 * STRH * 2 +
            ((lrow + lt8 * 8) * STRH + lt16 * 8) * 2;
        const __half* Ws = Wb + st * 64;

        // ---- S = Q @ K^T, both m-tiles; K b-frags loaded once ----
        float sc[2][8][4];
        #pragma unroll
        for (int mt = 0; mt < 2; ++mt)
            #pragma unroll
            for (int nt = 0; nt < 8; ++nt)
                sc[mt][nt][0] = sc[mt][nt][1] = sc[mt][nt][2] = sc[mt][nt][3] = 0.0f;
        #pragma unroll
        for (int kc = 0; kc < 4; ++kc) {
            uint32_t qa[2][4];
            ldsm4(qa[0], qsbase + (kc * 16) * 2);
            ldsm4(qa[1], qsbase + (16 * STRH + kc * 16) * 2);
            #pragma unroll
            for (int ntp = 0; ntp < 4; ++ntp) {
                uint32_t bk[4];
                ldsm4(bk, kbase + (ntp * 16 * STRH + kc * 16) * 2);
                mma_f16(sc[0][ntp * 2 + 0], qa[0], bk[0], bk[2]);
                mma_f16(sc[0][ntp * 2 + 1], qa[0], bk[1], bk[3]);
                mma_f16(sc[1][ntp * 2 + 0], qa[1], bk[0], bk[2]);
                mma_f16(sc[1][ntp * 2 + 1], qa[1], bk[1], bk[3]);
            }
        }

        // ---- P = 2^S, packed: pack S pairs to f16x2, one ex2.f16x2 each.
        //      p2[mt][nt][0] = P rows (g, g+8) cols (2t, 2t+1) packed, etc.
        uint32_t p2[2][8][2];
        #pragma unroll
        for (int mt = 0; mt < 2; ++mt)
            #pragma unroll
            for (int nt = 0; nt < 8; ++nt) {
                p2[mt][nt][0] = ex2h2(packh2(sc[mt][nt][0], sc[mt][nt][1]));
                p2[mt][nt][1] = ex2h2(packh2(sc[mt][nt][2], sc[mt][nt][3]));
            }

        // ---- O += P @ V' ; lsum += P @ w (both on tensor pipe) ----
        #pragma unroll
        for (int kc = 0; kc < 4; ++kc) {
            uint32_t pf[2][4];
            #pragma unroll
            for (int mt = 0; mt < 2; ++mt) {
                pf[mt][0] = p2[mt][2 * kc][0];
                pf[mt][1] = p2[mt][2 * kc][1];
                pf[mt][2] = p2[mt][2 * kc + 1][0];
                pf[mt][3] = p2[mt][2 * kc + 1][1];
            }
            // w b-frag: B[k][n] = w[k] (broadcast across n)
            const uint32_t w0 = *(const uint32_t*)&Ws[kc * 16 + 2 * t];
            const uint32_t w1 = *(const uint32_t*)&Ws[kc * 16 + 8 + 2 * t];
            mma_f16(lacc[0], pf[0], w0, w1);
            mma_f16(lacc[1], pf[1], w0, w1);
            #pragma unroll
            for (int nvp = 0; nvp < 4; ++nvp) {
                uint32_t bv[4];
                ldsm4(bv, vbase + (nvp * 16 * STRH + kc * 16) * 2);
                mma_f16(o[0][nvp * 2 + 0], pf[0], bv[0], bv[2]);
                mma_f16(o[0][nvp * 2 + 1], pf[0], bv[1], bv[3]);
                mma_f16(o[1][nvp * 2 + 0], pf[1], bv[0], bv[2]);
                mma_f16(o[1][nvp * 2 + 1], pf[1], bv[1], bv[3]);
            }
        }
    }

    // ---- epilogue: normalize by lacc row sums (columns replicated) ----
    #pragma unroll
    for (int mt = 0; mt < 2; ++mt) {
        const float inv0 = 1.0f / lacc[mt][0];  // row g
        const float inv1 = 1.0f / lacc[mt][2];  // row g+8
        const int srow = q0 + wid * 32 + mt * 16 + g;
        #pragma unroll
        for (int nv = 0; nv < 8; ++nv) {
            const int d0 = h * 64 + nv * 8 + 2 * t;
            float2 v0, v1;
            v0.x = o[mt][nv][0] * inv0; v0.y = o[mt][nv][1] * inv0;
            v1.x = o[mt][nv][2] * inv1; v1.y = o[mt][nv][3] * inv1;
            *(float2*)&out[((long long)(b * kS + srow)) * kD + d0] = v0;
            *(float2*)&out[((long long)(b * kS + srow + 8)) * kD + d0] = v1;
        }
    }
}

// ======================= launch =======================
extern "C" void kernel_launch(void* const* d_in, const int* in_sizes, int n_in,
                              void* d_out, int out_size)
{
    (void)in_sizes; (void)n_in; (void)out_size;
    const float* X    = (const float*)d_in[0];
    const float* mask = (const float*)d_in[1];
    const float* Wq   = (const float*)d_in[2];
    const float* bq   = (const float*)d_in[3];
    const float* Wk   = (const float*)d_in[4];
    const float* bk   = (const float*)d_in[5];
    const float* Wv   = (const float*)d_in[6];
    const float* bv   = (const float*)d_in[7];
    float* out = (float*)d_out;

    cudaFuncSetAttribute(qkv_kernel, cudaFuncAttributeMaxDynamicSharedMemorySize,
                         GEMM_SMEM_BYTES);
    cudaFuncSetAttribute(attn_kernel, cudaFuncAttributeMaxDynamicSharedMemorySize,
                         ATTN_SMEM_BYTES);

    prep_wt_kernel<<<dim3(32, 32, 3), 256>>>(Wq, Wk, Wv);
    prep_x_kernel<<<1024, 256>>>(X, mask);
    qkv_kernel<<<dim3(kD / 128, kM / 128, 3), 256, GEMM_SMEM_BYTES>>>(
        bq, bk, bv, mask);
    attn_kernel<<<dim3(kS / 128, kB * kH), 128, ATTN_SMEM_BYTES>>>(out);
}

// round 17
// speedup vs baseline: 1.5210x; 1.5210x over previous
#include <cuda_runtime.h>
#include <cuda_fp16.h>
#include <cstdint>

#define DEVINL __device__ __forceinline__

constexpr int kB = 4, kS = 2048, kD = 1024, kH = 16, kHD = 64;
constexpr int kM = kB * kS;  // 8192 rows for QKV GEMM
constexpr float kLog2e = 1.44269504088896f;

// All fp16 (same 10-bit mantissa as tf32):
// g_q, g_k : [B,H][S][64]   g_v : [B,H][64][S] (V^T, rows pre-scaled by
// e^mask -> mask folded into numerator)   g_x : rounded X
// g_wt : rounded W^T ([n][k]) per z.  Q pre-scaled by hd^-0.5 * log2(e).
// g_wexp[b][k] = fp16(e^mask) -> row-sum weights (denominator fold).
__device__ __half g_q[(long long)kB * kH * kS * kHD];
__device__ __half g_k[(long long)kB * kH * kS * kHD];
__device__ __half g_v[(long long)kB * kH * kS * kHD];
__device__ __half g_x[(long long)kM * kD];
__device__ __half g_wt[3ll * kD * kD];
__device__ __half g_wexp[kB * kS];

DEVINL uint32_t smem_u32(const void* p) {
    return (uint32_t)__cvta_generic_to_shared(p);
}
DEVINL void cp_async16(uint32_t dst, const void* src) {
    asm volatile("cp.async.cg.shared.global [%0], [%1], 16;\n" ::"r"(dst), "l"(src));
}
DEVINL void cp_commit() { asm volatile("cp.async.commit_group;\n" ::: "memory"); }
template <int N> DEVINL void cp_wait() {
    asm volatile("cp.async.wait_group %0;\n" ::"n"(N) : "memory");
}

DEVINL uint32_t packh2(float lo, float hi) {
    __half2 h = __floats2half2_rn(lo, hi);
    return *reinterpret_cast<uint32_t*>(&h);
}
DEVINL float ex2(float x) {
    float r;
    asm("ex2.approx.f32 %0, %1;" : "=f"(r) : "f"(x));
    return r;
}

DEVINL void mma_f16(float* c, const uint32_t* a, uint32_t b0, uint32_t b1) {
    asm volatile(
        "mma.sync.aligned.m16n8k16.row.col.f32.f16.f16.f32 "
        "{%0,%1,%2,%3}, {%4,%5,%6,%7}, {%8,%9}, {%0,%1,%2,%3};\n"
        : "+f"(c[0]), "+f"(c[1]), "+f"(c[2]), "+f"(c[3])
        : "r"(a[0]), "r"(a[1]), "r"(a[2]), "r"(a[3]), "r"(b0), "r"(b1));
}

DEVINL void ldsm4(uint32_t* r, uint32_t addr) {
    asm volatile(
        "ldmatrix.sync.aligned.m8n8.x4.shared.b16 {%0,%1,%2,%3}, [%4];\n"
        : "=r"(r[0]), "=r"(r[1]), "=r"(r[2]), "=r"(r[3]) : "r"(addr));
}

// ======================= Stage 0: prep =======================
__global__ __launch_bounds__(256) void prep_wt_kernel(
    const float* __restrict__ Wq, const float* __restrict__ Wk,
    const float* __restrict__ Wv)
{
    __shared__ float t[32][33];
    const int z = blockIdx.z;
    const float* W = (z == 0) ? Wq : (z == 1) ? Wk : Wv;
    __half* outp = g_wt + (long long)z * kD * kD;
    const int n0 = blockIdx.x * 32, k0 = blockIdx.y * 32;
    const int tx = threadIdx.x & 31, ty = threadIdx.x >> 5;  // 32 x 8
    #pragma unroll
    for (int r = ty; r < 32; r += 8)
        t[r][tx] = W[(long long)(k0 + r) * kD + n0 + tx];
    __syncthreads();
    #pragma unroll
    for (int r = ty; r < 32; r += 8)
        outp[(long long)(n0 + r) * kD + k0 + tx] = __float2half_rn(t[tx][r]);
}

__global__ __launch_bounds__(256) void prep_x_kernel(const float* __restrict__ X,
                                                     const float* __restrict__ mask)
{
    const long long n4 = (long long)kM * kD / 4;
    const float4* src = (const float4*)X;
    uint2* dst = (uint2*)g_x;
    for (long long i = blockIdx.x * 256 + threadIdx.x; i < n4;
         i += (long long)gridDim.x * 256) {
        float4 v = src[i];
        uint2 o;
        o.x = packh2(v.x, v.y);
        o.y = packh2(v.z, v.w);
        dst[i] = o;
    }
    // w = e^mask (row-sum weights), 8192 elements
    for (int i = blockIdx.x * 256 + threadIdx.x; i < kB * kS;
         i += gridDim.x * 256)
        g_wexp[i] = __float2half_rn(__expf(mask[i]));
}

// ======================= Stage 1: QKV projections (fp16 mma) ============
// 128x128 CTA tile, k-step 64, 2-stage ring, one barrier/iter, 2 CTAs/SM.
constexpr int STRH = 72;  // fp16 stride: 144B rows -> conflict-free ldmatrix
constexpr int GEMM_SMEM_BYTES = 2 * 2 * 128 * STRH * 2;  // 73728

__global__ __launch_bounds__(256) void qkv_kernel(
    const float* __restrict__ bq, const float* __restrict__ bk,
    const float* __restrict__ bv, const float* __restrict__ mask)
{
    extern __shared__ __align__(16) char smraw[];
    __half* As = (__half*)smraw;                 // 2 x 128 x STRH
    __half* Bs = As + 2 * 128 * STRH;            // 2 x 128 x STRH

    const int z = blockIdx.z;
    const float* bia = (z == 0) ? bq : (z == 1) ? bk : bv;
    __half* outp     = (z == 0) ? g_q : (z == 1) ? g_k : g_v;
    // Q pre-scaled by hd^-0.5 * log2e -> scores land in log2 domain.
    const float scl  = (z == 0) ? 0.125f * kLog2e : 1.0f;
    const __half* wt = g_wt + (long long)z * kD * kD;

    const int bm = blockIdx.y * 128;
    const int bn = blockIdx.x * 128;
    const int tid = threadIdx.x;
    const int wid = tid >> 5, lane = tid & 31;
    const int wm = (wid >> 2) * 64, wn = (wid & 3) * 32;
    const int g = lane >> 2, t = lane & 3;
    const int lrow = lane & 7;
    const int lt8 = (lane >> 3) & 1, lt16 = (lane >> 4) & 1;

    float acc[4][4][4];
    #pragma unroll
    for (int mt = 0; mt < 4; ++mt)
        #pragma unroll
        for (int nt = 0; nt < 4; ++nt)
            #pragma unroll
            for (int i = 0; i < 4; ++i) acc[mt][nt][i] = 0.0f;

    auto load_stage = [&](int st, int k0) {
        __half* A  = As + st * 128 * STRH;
        __half* Bm = Bs + st * 128 * STRH;
        #pragma unroll
        for (int c = 0; c < 4; ++c) {
            const int ch = tid + c * 256;
            const int r = ch >> 3, cc = (ch & 7) * 8;
            cp_async16(smem_u32(A + r * STRH + cc),
                       g_x + (long long)(bm + r) * kD + k0 + cc);
            cp_async16(smem_u32(Bm + r * STRH + cc),
                       wt + (long long)(bn + r) * kD + k0 + cc);
        }
        cp_commit();
    };

    load_stage(0, 0);
    #pragma unroll 1
    for (int i = 0; i < 16; ++i) {
        const int st = i & 1;
        cp_wait<0>();      // own chunks of stage i landed
        __syncthreads();   // stage i visible; all reads of stage i^1 done
        if (i + 1 < 16)
            load_stage(st ^ 1, (i + 1) * 64);  // overlaps compute below

        const uint32_t a_base = smem_u32(As) + st * 128 * STRH * 2 +
            ((wm + lrow + lt8 * 8) * STRH + lt16 * 8) * 2;
        const uint32_t b_base = smem_u32(Bs) + st * 128 * STRH * 2 +
            ((wn + lrow + lt8 * 8) * STRH + lt16 * 8) * 2;

        #pragma unroll
        for (int kc = 0; kc < 4; ++kc) {
            uint32_t af[4][4], bf[2][4];
            #pragma unroll
            for (int mt = 0; mt < 4; ++mt)
                ldsm4(af[mt], a_base + (mt * 16 * STRH + kc * 16) * 2);
            #pragma unroll
            for (int ntp = 0; ntp < 2; ++ntp)
                ldsm4(bf[ntp], b_base + (ntp * 16 * STRH + kc * 16) * 2);
            #pragma unroll
            for (int mt = 0; mt < 4; ++mt)
                #pragma unroll
                for (int ntp = 0; ntp < 2; ++ntp) {
                    mma_f16(acc[mt][ntp * 2 + 0], af[mt], bf[ntp][0], bf[ntp][2]);
                    mma_f16(acc[mt][ntp * 2 + 1], af[mt], bf[ntp][1], bf[ntp][3]);
                }
        }
    }

    // Epilogue: + bias, * scale (Q) or * e^mask (V), fp16-round, scatter.
    #pragma unroll
    for (int mt = 0; mt < 4; ++mt) {
        // per (mt, rr) the m-row (and thus key index ss) is fixed
        float wv[2] = {1.0f, 1.0f};
        int bbr[2], ssr[2];
        #pragma unroll
        for (int rr = 0; rr < 2; ++rr) {
            const int m = bm + wm + mt * 16 + g + rr * 8;
            bbr[rr] = m >> 11;
            ssr[rr] = m & 2047;
            if (z == 2) wv[rr] = __expf(mask[bbr[rr] * kS + ssr[rr]]);
        }
        #pragma unroll
        for (int nt = 0; nt < 4; ++nt) {
            const int col = bn + wn + nt * 8 + 2 * t;  // even
            const int hh = col >> 6, d0 = col & 63;
            const float b0 = bia[col], b1 = bia[col + 1];
            #pragma unroll
            for (int rr = 0; rr < 2; ++rr) {
                const int bb = bbr[rr], ss = ssr[rr];
                if (z < 2) {
                    __half2 v;
                    v.x = __float2half_rn((acc[mt][nt][rr * 2 + 0] + b0) * scl);
                    v.y = __float2half_rn((acc[mt][nt][rr * 2 + 1] + b1) * scl);
                    *(__half2*)&outp[((long long)(bb * kH + hh) * kS + ss) * kHD + d0] = v;
                } else {  // V^T: [b,h][d][s], rows scaled by e^mask
                    const long long base = ((long long)(bb * kH + hh) * kHD + d0) * kS + ss;
                    outp[base]      = __float2half_rn((acc[mt][nt][rr * 2 + 0] + b0) * wv[rr]);
                    outp[base + kS] = __float2half_rn((acc[mt][nt][rr * 2 + 1] + b1) * wv[rr]);
                }
            }
        }
    }
}

// ======================= Stage 2: flash attention (fp16 mma) ============
// CTA = (b,h, 128 q-rows), 4 warps x 32 rows (2 m-tiles). Fixed-max softmax
// P = 2^S with f32 ex2 (f16x2 MUFU path regressed in R16: latency chain).
// Q fragments REGISTER-RESIDENT (loaded once; 8 fewer LDSM/iter vs R15).
// Mask folded into V rows + row-sum weights w; row sums = P @ w on tensor
// pipe. 3-stage ring, one barrier/iter, K/V b-frags shared across m-tiles.
constexpr int ATTN_SMEM_BYTES =
    128 * STRH * 2 + 3 * (2 * 64 * STRH * 2) + 3 * 64 * 2;  // 74112

__global__ __launch_bounds__(128, 2) void attn_kernel(float* __restrict__ out)
{
    extern __shared__ __align__(16) char smraw[];
    __half* Qs = (__half*)smraw;          // 128 x STRH (staging only)
    __half* Kb = Qs + 128 * STRH;         // 3 x 64 x STRH (rows s, cols d)
    __half* Vb = Kb + 3 * 64 * STRH;      // 3 x 64 x STRH (rows d, cols s)
    __half* Wb = Vb + 3 * 64 * STRH;      // 3 x 64 (w = e^mask per key)

    const int bh = blockIdx.y;
    const int b = bh >> 4, h = bh & 15;
    const int q0 = blockIdx.x * 128;
    const int tid = threadIdx.x, wid = tid >> 5, lane = tid & 31;
    const int g = lane >> 2, t = lane & 3;
    const int lrow = lane & 7;
    const int lt8 = (lane >> 3) & 1, lt16 = (lane >> 4) & 1;

    const __half* qptr = g_q + ((long long)bh * kS + q0) * kHD;
    const __half* kptr = g_k + (long long)bh * kS * kHD;
    const __half* vptr = g_v + (long long)bh * kHD * kS;  // [d][s]
    const __half* wptr = g_wexp + b * kS;

    // ---- stage Q (128 x 64 fp16) into Qs, then grab register frags ----
    #pragma unroll
    for (int i = 0; i < 8; ++i) {
        const int ch = tid + i * 128;
        const int r = ch >> 3, c = (ch & 7) * 8;
        *(uint4*)&Qs[r * STRH + c] = *(const uint4*)&qptr[(long long)r * kHD + c];
    }

    auto prefetch = [&](int st, int k0) {
        __half* Kd = Kb + st * 64 * STRH;
        __half* Vd = Vb + st * 64 * STRH;
        #pragma unroll
        for (int i = 0; i < 4; ++i) {
            const int ch = tid + i * 128;
            const int r = ch >> 3, c = (ch & 7) * 8;
            cp_async16(smem_u32(Kd + r * STRH + c),
                       kptr + (long long)(k0 + r) * kHD + c);
            cp_async16(smem_u32(Vd + r * STRH + c),
                       vptr + (long long)r * kS + k0 + c);
        }
        if (tid < 8)
            cp_async16(smem_u32(Wb + st * 64 + tid * 8), wptr + k0 + tid * 8);
        cp_commit();
    };

    float o[2][8][4];
    #pragma unroll
    for (int mt = 0; mt < 2; ++mt)
        #pragma unroll
        for (int nv = 0; nv < 8; ++nv)
            #pragma unroll
            for (int i = 0; i < 4; ++i) o[mt][nv][i] = 0.0f;
    float lacc[2][4];  // row-sum c-frags (P @ w)
    #pragma unroll
    for (int mt = 0; mt < 2; ++mt)
        #pragma unroll
        for (int i = 0; i < 4; ++i) lacc[mt][i] = 0.0f;

    prefetch(0, 0);
    prefetch(1, 64);
    __syncthreads();  // Q staged + visible

    // Q fragments: register-resident for the whole mainloop (32 regs).
    uint32_t qf[2][4][4];
    {
        const uint32_t qsbase = smem_u32(Qs) +
            ((wid * 32 + lrow + lt8 * 8) * STRH + lt16 * 8) * 2;
        #pragma unroll
        for (int mt = 0; mt < 2; ++mt)
            #pragma unroll
            for (int kc = 0; kc < 4; ++kc)
                ldsm4(qf[mt][kc], qsbase + (mt * 16 * STRH + kc * 16) * 2);
    }

    constexpr int NIT = kS / 64;  // 32
    #pragma unroll 1
    for (int it = 0; it < NIT; ++it) {
        const int st = it - (it / 3) * 3;  // it % 3
        if (it + 2 < NIT) {
            cp_wait<1>();       // stage it's data landed (it+1 still pending)
            __syncthreads();    // publish stage it; fences reads of stage (it+2)%3
            const int st2 = (it + 2) - ((it + 2) / 3) * 3;
            prefetch(st2, (it + 2) * 64);
        } else {
            cp_wait<0>();
            __syncthreads();
        }

        const uint32_t kbase = smem_u32(Kb) + st * 64 * STRH * 2 +
            ((lrow + lt8 * 8) * STRH + lt16 * 8) * 2;
        const uint32_t vbase = smem_u32(Vb) + st * 64 * STRH * 2 +
            ((lrow + lt8 * 8) * STRH + lt16 * 8) * 2;
        const __half* Ws = Wb + st * 64;

        // ---- S = Q @ K^T, both m-tiles; K b-frags loaded once ----
        float sc[2][8][4];
        #pragma unroll
        for (int mt = 0; mt < 2; ++mt)
            #pragma unroll
            for (int nt = 0; nt < 8; ++nt)
                sc[mt][nt][0] = sc[mt][nt][1] = sc[mt][nt][2] = sc[mt][nt][3] = 0.0f;
        #pragma unroll
        for (int kc = 0; kc < 4; ++kc) {
            #pragma unroll
            for (int ntp = 0; ntp < 4; ++ntp) {
                uint32_t bk[4];
                ldsm4(bk, kbase + (ntp * 16 * STRH + kc * 16) * 2);
                mma_f16(sc[0][ntp * 2 + 0], qf[0][kc], bk[0], bk[2]);
                mma_f16(sc[0][ntp * 2 + 1], qf[0][kc], bk[1], bk[3]);
                mma_f16(sc[1][ntp * 2 + 0], qf[1][kc], bk[0], bk[2]);
                mma_f16(sc[1][ntp * 2 + 1], qf[1][kc], bk[1], bk[3]);
            }
        }

        // ---- P = 2^S (mask already folded into V rows + w weights) ----
        #pragma unroll
        for (int mt = 0; mt < 2; ++mt)
            #pragma unroll
            for (int nt = 0; nt < 8; ++nt) {
                sc[mt][nt][0] = ex2(sc[mt][nt][0]);
                sc[mt][nt][1] = ex2(sc[mt][nt][1]);
                sc[mt][nt][2] = ex2(sc[mt][nt][2]);
                sc[mt][nt][3] = ex2(sc[mt][nt][3]);
            }

        // ---- O += P @ V' ; lsum += P @ w (both on tensor pipe) ----
        #pragma unroll
        for (int kc = 0; kc < 4; ++kc) {
            uint32_t pf[2][4];
            #pragma unroll
            for (int mt = 0; mt < 2; ++mt) {
                pf[mt][0] = packh2(sc[mt][2 * kc][0],     sc[mt][2 * kc][1]);
                pf[mt][1] = packh2(sc[mt][2 * kc][2],     sc[mt][2 * kc][3]);
                pf[mt][2] = packh2(sc[mt][2 * kc + 1][0], sc[mt][2 * kc + 1][1]);
                pf[mt][3] = packh2(sc[mt][2 * kc + 1][2], sc[mt][2 * kc + 1][3]);
            }
            // w b-frag: B[k][n] = w[k] (broadcast across n)
            const uint32_t w0 = *(const uint32_t*)&Ws[kc * 16 + 2 * t];
            const uint32_t w1 = *(const uint32_t*)&Ws[kc * 16 + 8 + 2 * t];
            mma_f16(lacc[0], pf[0], w0, w1);
            mma_f16(lacc[1], pf[1], w0, w1);
            #pragma unroll
            for (int nvp = 0; nvp < 4; ++nvp) {
                uint32_t bv[4];
                ldsm4(bv, vbase + (nvp * 16 * STRH + kc * 16) * 2);
                mma_f16(o[0][nvp * 2 + 0], pf[0], bv[0], bv[2]);
                mma_f16(o[0][nvp * 2 + 1], pf[0], bv[1], bv[3]);
                mma_f16(o[1][nvp * 2 + 0], pf[1], bv[0], bv[2]);
                mma_f16(o[1][nvp * 2 + 1], pf[1], bv[1], bv[3]);
            }
        }
    }

    // ---- epilogue: normalize by lacc row sums (columns replicated) ----
    #pragma unroll
    for (int mt = 0; mt < 2; ++mt) {
        const float inv0 = 1.0f / lacc[mt][0];  // row g
        const float inv1 = 1.0f / lacc[mt][2];  // row g+8
        const int srow = q0 + wid * 32 + mt * 16 + g;
        #pragma unroll
        for (int nv = 0; nv < 8; ++nv) {
            const int d0 = h * 64 + nv * 8 + 2 * t;
            float2 v0, v1;
            v0.x = o[mt][nv][0] * inv0; v0.y = o[mt][nv][1] * inv0;
            v1.x = o[mt][nv][2] * inv1; v1.y = o[mt][nv][3] * inv1;
            *(float2*)&out[((long long)(b * kS + srow)) * kD + d0] = v0;
            *(float2*)&out[((long long)(b * kS + srow + 8)) * kD + d0] = v1;
        }
    }
}

// ======================= launch =======================
extern "C" void kernel_launch(void* const* d_in, const int* in_sizes, int n_in,
                              void* d_out, int out_size)
{
    (void)in_sizes; (void)n_in; (void)out_size;
    const float* X    = (const float*)d_in[0];
    const float* mask = (const float*)d_in[1];
    const float* Wq   = (const float*)d_in[2];
    const float* bq   = (const float*)d_in[3];
    const float* Wk   = (const float*)d_in[4];
    const float* bk   = (const float*)d_in[5];
    const float* Wv   = (const float*)d_in[6];
    const float* bv   = (const float*)d_in[7];
    float* out = (float*)d_out;

    cudaFuncSetAttribute(qkv_kernel, cudaFuncAttributeMaxDynamicSharedMemorySize,
                         GEMM_SMEM_BYTES);
    cudaFuncSetAttribute(attn_kernel, cudaFuncAttributeMaxDynamicSharedMemorySize,
                         ATTN_SMEM_BYTES);

    prep_wt_kernel<<<dim3(32, 32, 3), 256>>>(Wq, Wk, Wv);
    prep_x_kernel<<<1024, 256>>>(X, mask);
    qkv_kernel<<<dim3(kD / 128, kM / 128, 3), 256, GEMM_SMEM_BYTES>>>(
        bq, bk, bv, mask);
    attn_kernel<<<dim3(kS / 128, kB * kH), 128, ATTN_SMEM_BYTES>>>(out);
}